// round 9
// baseline (speedup 1.0000x reference)
#include <cuda_runtime.h>
#include <cuda_bf16.h>
#include <cstdint>
#include <math.h>

// Problem constants
#define B_  2
#define S_  2048
#define D_  1024
#define H_  16
#define C_  64
#define M_  (B_ * S_)      // 4096
#define N_  (H_ * C_)      // 1024

#define QSCALE 0.18033688011112042f   // C^-0.5 * log2(e)

// Scratch (device globals: allocation-free rule)
__device__ float g_q[M_ * N_];
__device__ float g_k[M_ * N_];
__device__ float g_v[M_ * N_];
__device__ float g_o[M_ * N_];
__device__ __nv_bfloat16 g_xh[M_ * D_], g_xl[M_ * D_];
__device__ __nv_bfloat16 g_oh[M_ * N_], g_ol[M_ * N_];
__device__ __nv_bfloat16 g_wth[4 * D_ * N_], g_wtl[4 * D_ * N_];  // W^T [n][k]

typedef unsigned long long u64;

// ===========================================================================
// fp32 -> (bf16 hi, bf16 lo) split helpers + kernels (unchanged)
// ===========================================================================
__device__ __forceinline__ void bf16split(float v, __nv_bfloat16& h, __nv_bfloat16& l) {
    h = __float2bfloat16_rn(v);
    l = __float2bfloat16_rn(v - __bfloat162float(h));
}

__global__ __launch_bounds__(256)
void split_kernel(const float* __restrict__ in, __nv_bfloat16* __restrict__ hi,
                  __nv_bfloat16* __restrict__ lo, int n4) {
    int i = blockIdx.x * 256 + threadIdx.x;
    if (i >= n4) return;
    float4 v = ((const float4*)in)[i];
    __nv_bfloat16 h0, l0, h1, l1, h2, l2, h3, l3;
    bf16split(v.x, h0, l0); bf16split(v.y, h1, l1);
    bf16split(v.z, h2, l2); bf16split(v.w, h3, l3);
    ((__nv_bfloat162*)hi)[2 * i]     = __nv_bfloat162(h0, h1);
    ((__nv_bfloat162*)hi)[2 * i + 1] = __nv_bfloat162(h2, h3);
    ((__nv_bfloat162*)lo)[2 * i]     = __nv_bfloat162(l0, l1);
    ((__nv_bfloat162*)lo)[2 * i + 1] = __nv_bfloat162(l2, l3);
}

// Transpose W[k][n] (1024x1024) -> Wt[n][k] with bf16 split. z selects weight.
__global__ __launch_bounds__(256)
void tsplit_kernel(const float* __restrict__ W0, const float* __restrict__ W1,
                   const float* __restrict__ W2, const float* __restrict__ W3,
                   __nv_bfloat16* __restrict__ oh, __nv_bfloat16* __restrict__ ol) {
    int z = blockIdx.z;
    const float* W = (z == 0) ? W0 : (z == 1) ? W1 : (z == 2) ? W2 : W3;
    __nv_bfloat16* outh = oh + (size_t)z * D_ * N_;
    __nv_bfloat16* outl = ol + (size_t)z * D_ * N_;
    __shared__ float t[32][33];
    int tx = threadIdx.x & 31, ty = threadIdx.x >> 5;
    int k0 = blockIdx.y * 32, n0 = blockIdx.x * 32;
#pragma unroll
    for (int i = 0; i < 32; i += 8)
        t[ty + i][tx] = W[(size_t)(k0 + ty + i) * 1024 + n0 + tx];
    __syncthreads();
#pragma unroll
    for (int i = 0; i < 32; i += 8) {
        float v = t[tx][ty + i];
        __nv_bfloat16 h, l;
        bf16split(v, h, l);
        size_t o = (size_t)(n0 + ty + i) * 1024 + k0 + tx;
        outh[o] = h;
        outl[o] = l;
    }
}

// ===========================================================================
// mma.sync helpers (BASE ISA — compiles for plain sm_103, runs on tensor pipe)
// ===========================================================================
__device__ __forceinline__ uint32_t smem_u32(const void* p) {
    uint32_t a;
    asm("{ .reg .u64 t; cvta.to.shared.u64 t, %1; cvt.u32.u64 %0, t; }"
        : "=r"(a) : "l"(p));
    return a;
}
__device__ __forceinline__ void ldmatrix_x4(uint32_t* r, uint32_t addr) {
    asm volatile("ldmatrix.sync.aligned.m8n8.x4.shared.b16 {%0,%1,%2,%3}, [%4];"
                 : "=r"(r[0]), "=r"(r[1]), "=r"(r[2]), "=r"(r[3]) : "r"(addr));
}
__device__ __forceinline__ void mma16816(float* d, const uint32_t* a, const uint32_t* b) {
    asm volatile(
        "mma.sync.aligned.m16n8k16.row.col.f32.bf16.bf16.f32 "
        "{%0,%1,%2,%3}, {%4,%5,%6,%7}, {%8,%9}, {%0,%1,%2,%3};"
        : "+f"(d[0]), "+f"(d[1]), "+f"(d[2]), "+f"(d[3])
        : "r"(a[0]), "r"(a[1]), "r"(a[2]), "r"(a[3]), "r"(b[0]), "r"(b[1]));
}

// ===========================================================================
// mma.sync GEMM: C[4096,1024] = alpha * (Ah+Al) @ (Bh+Bl)^T   (3-term split)
// A split [M,K] row-major bf16; Bt split [N,K] row-major bf16.
// CTA 128x128, BK=64, 8 warps as 4(m) x 2(n): warp tile 32x64.
// smem rows padded to 72 bf16 (144B = 36 banks) -> conflict-free ldmatrix.
// blockIdx.z selects {B slab, C output, alpha} (QKV fused in one launch).
// ===========================================================================
#define GSTRIDE 72
#define GE_AH 0
#define GE_AL (128 * GSTRIDE)
#define GE_BH (2 * 128 * GSTRIDE)
#define GE_BL (3 * 128 * GSTRIDE)
#define GEMM_SMEM_BYTES (4 * 128 * GSTRIDE * 2)   // 73728 B

__global__ __launch_bounds__(256)
void gemm_mma_kernel(const __nv_bfloat16* __restrict__ Ah,
                     const __nv_bfloat16* __restrict__ Al,
                     const __nv_bfloat16* __restrict__ Bth,
                     const __nv_bfloat16* __restrict__ Btl,
                     float* __restrict__ C0, float* __restrict__ C1,
                     float* __restrict__ C2, float alpha0) {
    extern __shared__ __nv_bfloat16 smg[];
    const uint32_t sbase = smem_u32(smg);

    int tid = threadIdx.x;
    int wid = tid >> 5, lane = tid & 31;
    int warp_m = (wid & 3) * 32;        // 4 warps down M
    int warp_n = (wid >> 2) * 64;       // 2 warps across N

    int z = blockIdx.z;
    const __nv_bfloat16* Bh = Bth + (size_t)z * D_ * N_;
    const __nv_bfloat16* Bl = Btl + (size_t)z * D_ * N_;
    float* C = (z == 0) ? C0 : (z == 1) ? C1 : C2;
    float alpha = (z == 0) ? alpha0 : 1.0f;

    const size_t arow0 = (size_t)blockIdx.y * 128;
    const size_t brow0 = (size_t)blockIdx.x * 128;

    float d[2][8][4];
#pragma unroll
    for (int t = 0; t < 2; t++)
#pragma unroll
        for (int j = 0; j < 8; j++)
#pragma unroll
            for (int e = 0; e < 4; e++) d[t][j][e] = 0.0f;

    // ldmatrix address components (element offsets within a tile)
    int a_row = lane & 15;                       // A: rows 0-15 twice
    int a_col = (lane >> 4) * 8;                 // then k+8 half
    int b_loc = lane & 7;                        // B: 4 matrices of 8 rows
    int b_mat = lane >> 3;
    int b_rowoff = (b_mat >> 1) * 8 + b_loc;     // n offset within 2-tile group
    int b_coloff = (b_mat & 1) * 8;              // k lo/hi

    for (int k0 = 0; k0 < 1024; k0 += 64) {
        __syncthreads();
        // Stage Ah/Al/Bh/Bl 128x64 tiles (uint4 = 8 bf16 per chunk)
        for (int i = tid; i < 1024; i += 256) {
            int row = i >> 3;
            int c8  = (i & 7) * 8;
            size_t ga = (arow0 + row) * 1024 + k0 + c8;
            size_t gb = (brow0 + row) * 1024 + k0 + c8;
            int so = row * GSTRIDE + c8;
            *(uint4*)(smg + GE_AH + so) = *(const uint4*)(Ah + ga);
            *(uint4*)(smg + GE_AL + so) = *(const uint4*)(Al + ga);
            *(uint4*)(smg + GE_BH + so) = *(const uint4*)(Bh + gb);
            *(uint4*)(smg + GE_BL + so) = *(const uint4*)(Bl + gb);
        }
        __syncthreads();

#pragma unroll
        for (int kk = 0; kk < 64; kk += 16) {
            uint32_t aH[2][4], aL[2][4];
#pragma unroll
            for (int t = 0; t < 2; t++) {
                int off = (warp_m + t * 16 + a_row) * GSTRIDE + kk + a_col;
                ldmatrix_x4(aH[t], sbase + (GE_AH + off) * 2);
                ldmatrix_x4(aL[t], sbase + (GE_AL + off) * 2);
            }
            uint32_t bH[8][2], bL[8][2];
#pragma unroll
            for (int jj = 0; jj < 8; jj += 2) {
                int off = (warp_n + jj * 8 + b_rowoff) * GSTRIDE + kk + b_coloff;
                uint32_t r[4];
                ldmatrix_x4(r, sbase + (GE_BH + off) * 2);
                bH[jj][0] = r[0]; bH[jj][1] = r[1];
                bH[jj + 1][0] = r[2]; bH[jj + 1][1] = r[3];
                ldmatrix_x4(r, sbase + (GE_BL + off) * 2);
                bL[jj][0] = r[0]; bL[jj][1] = r[1];
                bL[jj + 1][0] = r[2]; bL[jj + 1][1] = r[3];
            }
#pragma unroll
            for (int t = 0; t < 2; t++)
#pragma unroll
                for (int j = 0; j < 8; j++) {
                    mma16816(d[t][j], aH[t], bH[j]);   // Ah*Bh
                    mma16816(d[t][j], aH[t], bL[j]);   // Ah*Bl
                    mma16816(d[t][j], aL[t], bH[j]);   // Al*Bh
                }
        }
    }

    // Epilogue: d[t][j]: thread holds (row t/4 +{0,8}, col 2*(t%4)+{0,1})
    int er = lane >> 2;
    int ec = (lane & 3) * 2;
#pragma unroll
    for (int t = 0; t < 2; t++)
#pragma unroll
        for (int j = 0; j < 8; j++) {
            size_t row = arow0 + warp_m + t * 16 + er;
            size_t col = brow0 + warp_n + j * 8 + ec;
            *(float2*)(C + row * 1024 + col) =
                make_float2(alpha * d[t][j][0], alpha * d[t][j][1]);
            *(float2*)(C + (row + 8) * 1024 + col) =
                make_float2(alpha * d[t][j][2], alpha * d[t][j][3]);
        }
}

// ===========================================================================
// Flash attention (byte-identical to the R3 version that passed twice)
// ===========================================================================
__device__ __forceinline__ u64 pack2(float lo, float hi) {
    u64 r; asm("mov.b64 %0, {%1, %2};" : "=l"(r) : "f"(lo), "f"(hi)); return r;
}
__device__ __forceinline__ u64 dup2f(float v) { return pack2(v, v); }
__device__ __forceinline__ void unpack2(float& lo, float& hi, u64 v) {
    asm("mov.b64 {%0, %1}, %2;" : "=f"(lo), "=f"(hi) : "l"(v));
}
__device__ __forceinline__ u64 ffma2(u64 a, u64 b, u64 c) {
    u64 d; asm("fma.rn.f32x2 %0, %1, %2, %3;" : "=l"(d) : "l"(a), "l"(b), "l"(c));
    return d;
}
__device__ __forceinline__ u64 fmul2(u64 a, u64 b) {
    u64 d; asm("mul.rn.f32x2 %0, %1, %2;" : "=l"(d) : "l"(a), "l"(b));
    return d;
}

__device__ __forceinline__ float fexp2(float x) {
    x = fmaxf(x, -110.0f);
    float r = rintf(x);
    float f = x - r;
    float p =            1.5403530e-4f;
    p = fmaf(p, f,       1.3333558e-3f);
    p = fmaf(p, f,       9.6181291e-3f);
    p = fmaf(p, f,       5.5504109e-2f);
    p = fmaf(p, f,       2.4022651e-1f);
    p = fmaf(p, f,       6.9314718e-1f);
    p = fmaf(p, f,       1.0f);
    int e = (int)r;
    return __int_as_float(__float_as_int(p) + (e << 23));
}

#define QS_STRIDE 132
#define KS_STRIDE 65
#define PS_STRIDE 66
#define SM_QS 0
#define SM_KS (SM_QS + 64 * QS_STRIDE)
#define SM_VS (SM_KS + 64 * KS_STRIDE)
#define SM_PS (SM_VS + 64 * 64)
#define SM_FLOATS (SM_PS + 128 * PS_STRIDE)
#define ATTN_SMEM_BYTES (SM_FLOATS * 4)

__global__ __launch_bounds__(256, 2)
void attn_kernel(const float* __restrict__ Q, const float* __restrict__ K,
                 const float* __restrict__ V, float* __restrict__ O) {
    extern __shared__ float sm[];
    float* Qs = sm + SM_QS;
    float* Ks = sm + SM_KS;
    float* Vs = sm + SM_VS;
    float* Ps = sm + SM_PS;

    int qt = blockIdx.x;
    int h  = blockIdx.y;
    int b  = blockIdx.z;
    int tid = threadIdx.x;
    int tx = tid & 15;
    int ty = tid >> 4;

    const float* Qg = Q + (size_t)(b * S_ + qt * 128) * N_ + h * C_;
    const float* Kg = K + (size_t)(b * S_) * N_ + h * C_;
    const float* Vg = V + (size_t)(b * S_) * N_ + h * C_;

    for (int i = tid; i < 128 * 16; i += 256) {
        int row = i >> 4;
        int c4  = (i & 15) << 2;
        float4 q = *(const float4*)(Qg + (size_t)row * N_ + c4);
        Qs[(c4 + 0) * QS_STRIDE + row] = q.x;
        Qs[(c4 + 1) * QS_STRIDE + row] = q.y;
        Qs[(c4 + 2) * QS_STRIDE + row] = q.z;
        Qs[(c4 + 3) * QS_STRIDE + row] = q.w;
    }

    u64 o2[8][4];
    float mrow[8], lrow[8];
#pragma unroll
    for (int i = 0; i < 8; i++) {
        mrow[i] = -1e30f;
        lrow[i] = 0.0f;
#pragma unroll
        for (int u = 0; u < 4; u++) o2[i][u] = 0ull;
    }

    for (int kt = 0; kt < S_ / 64; kt++) {
        __syncthreads();
        const float* Kt = Kg + (size_t)kt * 64 * N_;
        const float* Vt = Vg + (size_t)kt * 64 * N_;
        for (int i = tid; i < 64 * 16; i += 256) {
            int row = i >> 4;
            int c4  = (i & 15) << 2;
            float4 kv = *(const float4*)(Kt + (size_t)row * N_ + c4);
            Ks[row * KS_STRIDE + c4 + 0] = kv.x;
            Ks[row * KS_STRIDE + c4 + 1] = kv.y;
            Ks[row * KS_STRIDE + c4 + 2] = kv.z;
            Ks[row * KS_STRIDE + c4 + 3] = kv.w;
            float4 vv = *(const float4*)(Vt + (size_t)row * N_ + c4);
            *(float4*)(Vs + row * 64 + c4) = vv;
        }
        __syncthreads();

        u64 s2[4][4];
#pragma unroll
        for (int i = 0; i < 4; i++)
#pragma unroll
            for (int j = 0; j < 4; j++) s2[i][j] = 0ull;

#pragma unroll 8
        for (int c = 0; c < 64; c++) {
            ulonglong2 qa = *(ulonglong2*)(Qs + c * QS_STRIDE + ty * 8);
            ulonglong2 qb = *(ulonglong2*)(Qs + c * QS_STRIDE + ty * 8 + 4);
            u64 q2[4] = {qa.x, qa.y, qb.x, qb.y};
            u64 k2[4];
#pragma unroll
            for (int j = 0; j < 4; j++)
                k2[j] = dup2f(Ks[(tx * 4 + j) * KS_STRIDE + c]);
#pragma unroll
            for (int i = 0; i < 4; i++)
#pragma unroll
                for (int j = 0; j < 4; j++)
                    s2[i][j] = ffma2(q2[i], k2[j], s2[i][j]);
        }

        float s[8][4];
#pragma unroll
        for (int i2 = 0; i2 < 4; i2++)
#pragma unroll
            for (int j = 0; j < 4; j++)
                unpack2(s[2 * i2][j], s[2 * i2 + 1][j], s2[i2][j]);

#pragma unroll
        for (int i = 0; i < 8; i++) {
            float mx = fmaxf(fmaxf(s[i][0], s[i][1]), fmaxf(s[i][2], s[i][3]));
            mx = fmaxf(mx, __shfl_xor_sync(0xffffffffu, mx, 8));
            mx = fmaxf(mx, __shfl_xor_sync(0xffffffffu, mx, 4));
            mx = fmaxf(mx, __shfl_xor_sync(0xffffffffu, mx, 2));
            mx = fmaxf(mx, __shfl_xor_sync(0xffffffffu, mx, 1));
            float mnew = fmaxf(mrow[i], mx);
            float corr = fexp2(mrow[i] - mnew);
            float p0 = fexp2(s[i][0] - mnew);
            float p1 = fexp2(s[i][1] - mnew);
            float p2 = fexp2(s[i][2] - mnew);
            float p3 = fexp2(s[i][3] - mnew);
            float rs = (p0 + p1) + (p2 + p3);
            rs += __shfl_xor_sync(0xffffffffu, rs, 8);
            rs += __shfl_xor_sync(0xffffffffu, rs, 4);
            rs += __shfl_xor_sync(0xffffffffu, rs, 2);
            rs += __shfl_xor_sync(0xffffffffu, rs, 1);
            lrow[i] = lrow[i] * corr + rs;
            mrow[i] = mnew;
            u64 c2 = dup2f(corr);
#pragma unroll
            for (int u = 0; u < 4; u++) o2[i][u] = fmul2(o2[i][u], c2);
            int row = ty * 8 + i;
            *(u64*)(Ps + row * PS_STRIDE + tx * 4)     = pack2(p0, p1);
            *(u64*)(Ps + row * PS_STRIDE + tx * 4 + 2) = pack2(p2, p3);
        }
        __syncthreads();

#pragma unroll 4
        for (int j = 0; j < 64; j += 2) {
            float4 va = *(float4*)(Vs + j * 64 + tx * 4);
            float4 vb = *(float4*)(Vs + (j + 1) * 64 + tx * 4);
            u64 v2[4] = {pack2(va.x, vb.x), pack2(va.y, vb.y),
                         pack2(va.z, vb.z), pack2(va.w, vb.w)};
#pragma unroll
            for (int i = 0; i < 8; i++) {
                u64 p2 = *(u64*)(Ps + (ty * 8 + i) * PS_STRIDE + j);
#pragma unroll
                for (int u = 0; u < 4; u++)
                    o2[i][u] = ffma2(p2, v2[u], o2[i][u]);
            }
        }
    }

#pragma unroll
    for (int i = 0; i < 8; i++) {
        float inv = 1.0f / lrow[i];
        float r[4];
#pragma unroll
        for (int u = 0; u < 4; u++) {
            float lo, hi;
            unpack2(lo, hi, o2[i][u]);
            r[u] = (lo + hi) * inv;
        }
        int row = qt * 128 + ty * 8 + i;
        *(float4*)(O + (size_t)(b * S_ + row) * N_ + h * C_ + tx * 4) =
            make_float4(r[0], r[1], r[2], r[3]);
    }
}

// ===========================================================================
extern "C" void kernel_launch(void* const* d_in, const int* in_sizes, int n_in,
                              void* d_out, int out_size) {
    const float* x  = (const float*)d_in[0];
    const float* Wq = (const float*)d_in[1];
    const float* Wk = (const float*)d_in[2];
    const float* Wv = (const float*)d_in[3];
    const float* Wo = (const float*)d_in[4];
    float* out = (float*)d_out;

    float *q, *k, *v, *o;
    __nv_bfloat16 *xh, *xl, *oh, *ol, *wth, *wtl;
    cudaGetSymbolAddress((void**)&q, g_q);
    cudaGetSymbolAddress((void**)&k, g_k);
    cudaGetSymbolAddress((void**)&v, g_v);
    cudaGetSymbolAddress((void**)&o, g_o);
    cudaGetSymbolAddress((void**)&xh, g_xh);
    cudaGetSymbolAddress((void**)&xl, g_xl);
    cudaGetSymbolAddress((void**)&oh, g_oh);
    cudaGetSymbolAddress((void**)&ol, g_ol);
    cudaGetSymbolAddress((void**)&wth, g_wth);
    cudaGetSymbolAddress((void**)&wtl, g_wtl);

    cudaFuncSetAttribute(attn_kernel,
                         cudaFuncAttributeMaxDynamicSharedMemorySize,
                         ATTN_SMEM_BYTES);
    cudaFuncSetAttribute(gemm_mma_kernel,
                         cudaFuncAttributeMaxDynamicSharedMemorySize,
                         GEMM_SMEM_BYTES);

    // 1. Split x into bf16 hi/lo
    split_kernel<<<(M_ * D_ / 4 + 255) / 256, 256>>>(x, xh, xl, M_ * D_ / 4);

    // 2. Transpose + split the 4 weight matrices -> [n][k] bf16
    tsplit_kernel<<<dim3(32, 32, 4), 256>>>(Wq, Wk, Wv, Wo, wth, wtl);

    // 3. QKV projections via mma.sync (z selects weight slab + output)
    gemm_mma_kernel<<<dim3(8, 32, 3), 256, GEMM_SMEM_BYTES>>>(
        xh, xl, wth, wtl, q, k, v, QSCALE);

    // 4. Flash attention (fp32 SIMT)
    dim3 ga(S_ / 128, H_, B_);
    attn_kernel<<<ga, 256, ATTN_SMEM_BYTES>>>(q, k, v, o);

    // 5. Split attention output
    split_kernel<<<(M_ * N_ / 4 + 255) / 256, 256>>>(o, oh, ol, M_ * N_ / 4);

    // 6. Output projection via mma.sync (Wo slab is z=3)
    gemm_mma_kernel<<<dim3(8, 32, 1), 256, GEMM_SMEM_BYTES>>>(
        oh, ol, wth + (size_t)3 * D_ * N_, wtl + (size_t)3 * D_ * N_,
        out, nullptr, nullptr, 1.0f);
}

// round 12
// speedup vs baseline: 1.9827x; 1.9827x over previous
#include <cuda_runtime.h>
#include <cuda_bf16.h>
#include <cstdint>
#include <math.h>

// Problem constants
#define B_  2
#define S_  2048
#define D_  1024
#define H_  16
#define C_  64
#define M_  (B_ * S_)      // 4096
#define N_  (H_ * C_)      // 1024

#define QSCALE 0.18033688011112042f   // C^-0.5 * log2(e)

// Scratch (device globals: allocation-free rule)
__device__ __nv_bfloat16 g_qh[M_ * N_], g_ql[M_ * N_];
__device__ __nv_bfloat16 g_kh[M_ * N_], g_kl[M_ * N_];
__device__ __nv_bfloat16 g_vh[M_ * N_], g_vl[M_ * N_];
__device__ __nv_bfloat16 g_oh[M_ * N_], g_ol[M_ * N_];
__device__ __nv_bfloat16 g_xh[M_ * D_], g_xl[M_ * D_];
__device__ __nv_bfloat16 g_wth[4 * D_ * N_], g_wtl[4 * D_ * N_];  // W^T [n][k]

// ===========================================================================
// Base-ISA PTX helpers (ldmatrix/mma path validated on this toolchain in R9)
// ===========================================================================
__device__ __forceinline__ uint32_t smem_u32(const void* p) {
    uint32_t a;
    asm("{ .reg .u64 t; cvta.to.shared.u64 t, %1; cvt.u32.u64 %0, t; }"
        : "=r"(a) : "l"(p));
    return a;
}
__device__ __forceinline__ void ldmatrix_x4(uint32_t* r, uint32_t addr) {
    asm volatile("ldmatrix.sync.aligned.m8n8.x4.shared.b16 {%0,%1,%2,%3}, [%4];"
                 : "=r"(r[0]), "=r"(r[1]), "=r"(r[2]), "=r"(r[3]) : "r"(addr));
}
__device__ __forceinline__ void ldmatrix_x4t(uint32_t* r, uint32_t addr) {
    asm volatile("ldmatrix.sync.aligned.m8n8.x4.trans.shared.b16 {%0,%1,%2,%3}, [%4];"
                 : "=r"(r[0]), "=r"(r[1]), "=r"(r[2]), "=r"(r[3]) : "r"(addr));
}
__device__ __forceinline__ void mma16816(float* d, const uint32_t* a, const uint32_t* b) {
    asm volatile(
        "mma.sync.aligned.m16n8k16.row.col.f32.bf16.bf16.f32 "
        "{%0,%1,%2,%3}, {%4,%5,%6,%7}, {%8,%9}, {%0,%1,%2,%3};"
        : "+f"(d[0]), "+f"(d[1]), "+f"(d[2]), "+f"(d[3])
        : "r"(a[0]), "r"(a[1]), "r"(a[2]), "r"(a[3]), "r"(b[0]), "r"(b[1]));
}
__device__ __forceinline__ void cp_async16(uint32_t saddr, const void* gaddr) {
    asm volatile("cp.async.cg.shared.global [%0], [%1], 16;"
                 :: "r"(saddr), "l"(gaddr));
}
#define CP_COMMIT() asm volatile("cp.async.commit_group;" ::: "memory")
#define CP_WAIT(N)  asm volatile("cp.async.wait_group %0;" :: "n"(N) : "memory")

__device__ __forceinline__ uint32_t packbf2(float a, float b) {
    __nv_bfloat162 t(__float2bfloat16_rn(a), __float2bfloat16_rn(b));
    return *(uint32_t*)&t;
}

// Fast exp2 on the FMA pipe. Valid for x <= 0. Max rel err ~1.5e-7.
__device__ __forceinline__ float fexp2(float x) {
    x = fmaxf(x, -110.0f);
    float r = rintf(x);
    float f = x - r;
    float p =            1.5403530e-4f;
    p = fmaf(p, f,       1.3333558e-3f);
    p = fmaf(p, f,       9.6181291e-3f);
    p = fmaf(p, f,       5.5504109e-2f);
    p = fmaf(p, f,       2.4022651e-1f);
    p = fmaf(p, f,       6.9314718e-1f);
    p = fmaf(p, f,       1.0f);
    return __int_as_float(__float_as_int(p) + (((int)r) << 23));
}

// ===========================================================================
// fp32 -> (bf16 hi, bf16 lo) split kernels
// ===========================================================================
__device__ __forceinline__ void bf16split(float v, __nv_bfloat16& h, __nv_bfloat16& l) {
    h = __float2bfloat16_rn(v);
    l = __float2bfloat16_rn(v - __bfloat162float(h));
}

__global__ __launch_bounds__(256)
void split_kernel(const float* __restrict__ in, __nv_bfloat16* __restrict__ hi,
                  __nv_bfloat16* __restrict__ lo, int n4) {
    int i = blockIdx.x * 256 + threadIdx.x;
    if (i >= n4) return;
    float4 v = ((const float4*)in)[i];
    __nv_bfloat16 h0, l0, h1, l1, h2, l2, h3, l3;
    bf16split(v.x, h0, l0); bf16split(v.y, h1, l1);
    bf16split(v.z, h2, l2); bf16split(v.w, h3, l3);
    ((__nv_bfloat162*)hi)[2 * i]     = __nv_bfloat162(h0, h1);
    ((__nv_bfloat162*)hi)[2 * i + 1] = __nv_bfloat162(h2, h3);
    ((__nv_bfloat162*)lo)[2 * i]     = __nv_bfloat162(l0, l1);
    ((__nv_bfloat162*)lo)[2 * i + 1] = __nv_bfloat162(l2, l3);
}

__global__ __launch_bounds__(256)
void tsplit_kernel(const float* __restrict__ W0, const float* __restrict__ W1,
                   const float* __restrict__ W2, const float* __restrict__ W3,
                   __nv_bfloat16* __restrict__ oh, __nv_bfloat16* __restrict__ ol) {
    int z = blockIdx.z;
    const float* W = (z == 0) ? W0 : (z == 1) ? W1 : (z == 2) ? W2 : W3;
    __nv_bfloat16* outh = oh + (size_t)z * D_ * N_;
    __nv_bfloat16* outl = ol + (size_t)z * D_ * N_;
    __shared__ float t[32][33];
    int tx = threadIdx.x & 31, ty = threadIdx.x >> 5;
    int k0 = blockIdx.y * 32, n0 = blockIdx.x * 32;
#pragma unroll
    for (int i = 0; i < 32; i += 8)
        t[ty + i][tx] = W[(size_t)(k0 + ty + i) * 1024 + n0 + tx];
    __syncthreads();
#pragma unroll
    for (int i = 0; i < 32; i += 8) {
        float v = t[tx][ty + i];
        __nv_bfloat16 h, l;
        bf16split(v, h, l);
        size_t o = (size_t)(n0 + ty + i) * 1024 + k0 + tx;
        outh[o] = h;
        outl[o] = l;
    }
}

// ===========================================================================
// mma.sync GEMM (R9-validated core). 3-term split, CTA 128x128, BK=64.
// Split-output mode (Cf==null): writes bf16 hi/lo pair arrays.
// fp32 mode (Cf!=null): writes fp32 (final projection -> d_out).
// ===========================================================================
#define GSTRIDE 72
#define GE_AH 0
#define GE_AL (128 * GSTRIDE)
#define GE_BH (2 * 128 * GSTRIDE)
#define GE_BL (3 * 128 * GSTRIDE)
#define GEMM_SMEM_BYTES (4 * 128 * GSTRIDE * 2)   // 73728 B

__global__ __launch_bounds__(256)
void gemm_mma_kernel(const __nv_bfloat16* __restrict__ Ah,
                     const __nv_bfloat16* __restrict__ Al,
                     const __nv_bfloat16* __restrict__ Bth,
                     const __nv_bfloat16* __restrict__ Btl,
                     __nv_bfloat16* __restrict__ Oh0, __nv_bfloat16* __restrict__ Ol0,
                     __nv_bfloat16* __restrict__ Oh1, __nv_bfloat16* __restrict__ Ol1,
                     __nv_bfloat16* __restrict__ Oh2, __nv_bfloat16* __restrict__ Ol2,
                     float* __restrict__ Cf, float alpha0) {
    extern __shared__ __nv_bfloat16 smg[];
    const uint32_t sbase = smem_u32(smg);

    int tid = threadIdx.x;
    int wid = tid >> 5, lane = tid & 31;
    int warp_m = (wid & 3) * 32;
    int warp_n = (wid >> 2) * 64;

    int z = blockIdx.z;
    const __nv_bfloat16* Bh = Bth + (size_t)z * D_ * N_;
    const __nv_bfloat16* Bl = Btl + (size_t)z * D_ * N_;
    __nv_bfloat16* Oh = (z == 0) ? Oh0 : (z == 1) ? Oh1 : Oh2;
    __nv_bfloat16* Ol = (z == 0) ? Ol0 : (z == 1) ? Ol1 : Ol2;
    float alpha = (z == 0) ? alpha0 : 1.0f;

    const size_t arow0 = (size_t)blockIdx.y * 128;
    const size_t brow0 = (size_t)blockIdx.x * 128;

    float d[2][8][4];
#pragma unroll
    for (int t = 0; t < 2; t++)
#pragma unroll
        for (int j = 0; j < 8; j++)
#pragma unroll
            for (int e = 0; e < 4; e++) d[t][j][e] = 0.0f;

    int a_row = lane & 15;
    int a_col = (lane >> 4) * 8;
    int b_loc = lane & 7;
    int b_mat = lane >> 3;
    int b_rowoff = (b_mat >> 1) * 8 + b_loc;
    int b_coloff = (b_mat & 1) * 8;

    for (int k0 = 0; k0 < 1024; k0 += 64) {
        __syncthreads();
        for (int i = tid; i < 1024; i += 256) {
            int row = i >> 3;
            int c8  = (i & 7) * 8;
            size_t ga = (arow0 + row) * 1024 + k0 + c8;
            size_t gb = (brow0 + row) * 1024 + k0 + c8;
            int so = row * GSTRIDE + c8;
            *(uint4*)(smg + GE_AH + so) = *(const uint4*)(Ah + ga);
            *(uint4*)(smg + GE_AL + so) = *(const uint4*)(Al + ga);
            *(uint4*)(smg + GE_BH + so) = *(const uint4*)(Bh + gb);
            *(uint4*)(smg + GE_BL + so) = *(const uint4*)(Bl + gb);
        }
        __syncthreads();

#pragma unroll
        for (int kk = 0; kk < 64; kk += 16) {
            uint32_t aH[2][4], aL[2][4];
#pragma unroll
            for (int t = 0; t < 2; t++) {
                int off = (warp_m + t * 16 + a_row) * GSTRIDE + kk + a_col;
                ldmatrix_x4(aH[t], sbase + (GE_AH + off) * 2);
                ldmatrix_x4(aL[t], sbase + (GE_AL + off) * 2);
            }
            uint32_t bH[8][2], bL[8][2];
#pragma unroll
            for (int jj = 0; jj < 8; jj += 2) {
                int off = (warp_n + jj * 8 + b_rowoff) * GSTRIDE + kk + b_coloff;
                uint32_t r[4];
                ldmatrix_x4(r, sbase + (GE_BH + off) * 2);
                bH[jj][0] = r[0]; bH[jj][1] = r[1];
                bH[jj + 1][0] = r[2]; bH[jj + 1][1] = r[3];
                ldmatrix_x4(r, sbase + (GE_BL + off) * 2);
                bL[jj][0] = r[0]; bL[jj][1] = r[1];
                bL[jj + 1][0] = r[2]; bL[jj + 1][1] = r[3];
            }
#pragma unroll
            for (int t = 0; t < 2; t++)
#pragma unroll
                for (int j = 0; j < 8; j++) {
                    mma16816(d[t][j], aH[t], bH[j]);
                    mma16816(d[t][j], aH[t], bL[j]);
                    mma16816(d[t][j], aL[t], bH[j]);
                }
        }
    }

    int er = lane >> 2;
    int ec = (lane & 3) * 2;
#pragma unroll
    for (int t = 0; t < 2; t++)
#pragma unroll
        for (int j = 0; j < 8; j++) {
            size_t row = arow0 + warp_m + t * 16 + er;
            size_t col = brow0 + warp_n + j * 8 + ec;
            float v0 = alpha * d[t][j][0], v1 = alpha * d[t][j][1];
            float v2 = alpha * d[t][j][2], v3 = alpha * d[t][j][3];
            if (Cf) {
                *(float2*)(Cf + row * 1024 + col)       = make_float2(v0, v1);
                *(float2*)(Cf + (row + 8) * 1024 + col) = make_float2(v2, v3);
            } else {
                __nv_bfloat16 h0, l0, h1, l1, h2, l2, h3, l3;
                bf16split(v0, h0, l0); bf16split(v1, h1, l1);
                bf16split(v2, h2, l2); bf16split(v3, h3, l3);
                *(__nv_bfloat162*)(Oh + row * 1024 + col)       = __nv_bfloat162(h0, h1);
                *(__nv_bfloat162*)(Ol + row * 1024 + col)       = __nv_bfloat162(l0, l1);
                *(__nv_bfloat162*)(Oh + (row + 8) * 1024 + col) = __nv_bfloat162(h2, h3);
                *(__nv_bfloat162*)(Ol + (row + 8) * 1024 + col) = __nv_bfloat162(l2, l3);
            }
        }
}

// ===========================================================================
// Tensor-core flash attention (FA2-style, mma.sync + ldmatrix).
// Block = (qt, h, b): 128 queries, 8 warps x 16 rows. 64-key tiles,
// cp.async double-buffered. 3-term bf16 splits for QK^T and P@V.
// P accumulator fragments -> A fragments in registers (no smem round trip).
// ===========================================================================
#define AROWB 144                      // 72 bf16 per smem row (16B-aligned, LDSM conflict-free)
#define STAGE_BYTES (4 * 64 * AROWB)   // Kh,Kl,Vh,Vl tiles: 36864 B
#define ATT_SMEM_BYTES (2 * STAGE_BYTES)

__global__ __launch_bounds__(256)
void attn_mma_kernel(const __nv_bfloat16* __restrict__ Qh, const __nv_bfloat16* __restrict__ Ql,
                     const __nv_bfloat16* __restrict__ Kh, const __nv_bfloat16* __restrict__ Kl,
                     const __nv_bfloat16* __restrict__ Vh, const __nv_bfloat16* __restrict__ Vl,
                     __nv_bfloat16* __restrict__ Ohi, __nv_bfloat16* __restrict__ Olo) {
    extern __shared__ char sm[];
    const uint32_t sb = smem_u32(sm);

    int tid = threadIdx.x;
    int w = tid >> 5, lane = tid & 31;
    int qt = blockIdx.x, h = blockIdx.y, b = blockIdx.z;

    const size_t qrow0 = (size_t)(b * S_ + qt * 128);
    const size_t krow0 = (size_t)(b * S_);
    const int    hc    = h * 64;

    // ---- Stage Q (bf16 hi/lo) into stage-0 region: Qh [128][72] @0, Ql @18432
#pragma unroll
    for (int t = 0; t < 8; t++) {
        int a   = t >> 2;                    // 0: Qh, 1: Ql
        int rem = (t & 3) * 256 + tid;       // 0..1023
        int row = rem >> 3, ch = rem & 7;
        const __nv_bfloat16* src = a ? Ql : Qh;
        cp_async16(sb + a * 18432 + row * AROWB + ch * 16,
                   src + (qrow0 + row) * 1024 + hc + ch * 8);
    }
    CP_COMMIT();
    CP_WAIT(0);
    __syncthreads();

    // ---- Q fragments to registers (held for whole kernel)
    int li = lane & 7, lt = lane >> 3;
    int qoff = ((lt & 1) * 8 + li) * AROWB + (lt >> 1) * 16;   // A-frag / trans-B addressing
    int koff = ((lt >> 1) * 8 + li) * AROWB + (lt & 1) * 16;   // B-frag addressing
    uint32_t qfh[4][4], qfl[4][4];
#pragma unroll
    for (int kk = 0; kk < 4; kk++) {
        ldmatrix_x4(qfh[kk], sb +         w * (16 * AROWB) + kk * 32 + qoff);
        ldmatrix_x4(qfl[kk], sb + 18432 + w * (16 * AROWB) + kk * 32 + qoff);
    }
    __syncthreads();   // stage-0 free for K/V

    // ---- Prefetch key tile 0 -> stage 0
#pragma unroll
    for (int t = 0; t < 8; t++) {
        int a = t >> 1;
        int rem = (t & 1) * 256 + tid;
        int row = rem >> 3, ch = rem & 7;
        const __nv_bfloat16* src = (a == 0) ? Kh : (a == 1) ? Kl : (a == 2) ? Vh : Vl;
        cp_async16(sb + a * 9216 + row * AROWB + ch * 16,
                   src + (krow0 + row) * 1024 + hc + ch * 8);
    }
    CP_COMMIT();

    float o[8][4];
#pragma unroll
    for (int n = 0; n < 8; n++)
#pragma unroll
        for (int e = 0; e < 4; e++) o[n][e] = 0.0f;
    float mA = -1e30f, mB = -1e30f, lA = 0.0f, lB = 0.0f;

    for (int kt = 0; kt < 32; kt++) {
        int cur = kt & 1;
        __syncthreads();   // everyone done reading buf[(kt+1)&1] (prev iter)
        if (kt + 1 < 32) {
            uint32_t nsb = sb + ((kt + 1) & 1) * STAGE_BYTES;
            size_t krow = krow0 + (size_t)(kt + 1) * 64;
#pragma unroll
            for (int t = 0; t < 8; t++) {
                int a = t >> 1;
                int rem = (t & 1) * 256 + tid;
                int row = rem >> 3, ch = rem & 7;
                const __nv_bfloat16* src = (a == 0) ? Kh : (a == 1) ? Kl : (a == 2) ? Vh : Vl;
                cp_async16(nsb + a * 9216 + row * AROWB + ch * 16,
                           src + (krow + row) * 1024 + hc + ch * 8);
            }
        }
        CP_COMMIT();
        CP_WAIT(1);        // current tile resident (groups retire in order)
        __syncthreads();

        uint32_t Kb  = sb + cur * STAGE_BYTES;
        uint32_t Klb = Kb + 9216, Vhb = Kb + 18432, Vlb = Kb + 27648;

        // ---- S = Q K^T (3-term). s[j]: n-tile j = keys 8j..8j+7
        float s[8][4];
#pragma unroll
        for (int j = 0; j < 8; j++)
#pragma unroll
            for (int e = 0; e < 4; e++) s[j][e] = 0.0f;

#pragma unroll
        for (int kk = 0; kk < 4; kk++)
#pragma unroll
            for (int jp = 0; jp < 4; jp++) {
                uint32_t base = jp * (16 * AROWB) + kk * 32 + koff;
                uint32_t kh4[4], kl4[4];
                ldmatrix_x4(kh4, Kb + base);
                ldmatrix_x4(kl4, Klb + base);
                mma16816(s[2 * jp],     qfh[kk], kh4);
                mma16816(s[2 * jp + 1], qfh[kk], kh4 + 2);
                mma16816(s[2 * jp],     qfh[kk], kl4);
                mma16816(s[2 * jp + 1], qfh[kk], kl4 + 2);
                mma16816(s[2 * jp],     qfl[kk], kh4);
                mma16816(s[2 * jp + 1], qfl[kk], kh4 + 2);
            }

        // ---- Online softmax (rows g = lane>>2 and g+8)
        float mxA = -1e30f, mxB = -1e30f;
#pragma unroll
        for (int j = 0; j < 8; j++) {
            mxA = fmaxf(mxA, fmaxf(s[j][0], s[j][1]));
            mxB = fmaxf(mxB, fmaxf(s[j][2], s[j][3]));
        }
        mxA = fmaxf(mxA, __shfl_xor_sync(0xffffffffu, mxA, 1));
        mxA = fmaxf(mxA, __shfl_xor_sync(0xffffffffu, mxA, 2));
        mxB = fmaxf(mxB, __shfl_xor_sync(0xffffffffu, mxB, 1));
        mxB = fmaxf(mxB, __shfl_xor_sync(0xffffffffu, mxB, 2));
        float mnA = fmaxf(mA, mxA), mnB = fmaxf(mB, mxB);
        float corrA = fexp2(mA - mnA), corrB = fexp2(mB - mnB);
        mA = mnA; mB = mnB;

        float rsA = 0.0f, rsB = 0.0f;
        uint32_t ph[8][2], pl[8][2];
#pragma unroll
        for (int j = 0; j < 8; j++) {
            float p0 = fexp2(s[j][0] - mnA);
            float p1 = fexp2(s[j][1] - mnA);
            float p2 = fexp2(s[j][2] - mnB);
            float p3 = fexp2(s[j][3] - mnB);
            rsA += p0 + p1;
            rsB += p2 + p3;
            __nv_bfloat16 h0 = __float2bfloat16_rn(p0), h1 = __float2bfloat16_rn(p1);
            __nv_bfloat16 h2 = __float2bfloat16_rn(p2), h3 = __float2bfloat16_rn(p3);
            ph[j][0] = packbf2(p0, p1);
            ph[j][1] = packbf2(p2, p3);
            pl[j][0] = packbf2(p0 - __bfloat162float(h0), p1 - __bfloat162float(h1));
            pl[j][1] = packbf2(p2 - __bfloat162float(h2), p3 - __bfloat162float(h3));
        }
        rsA += __shfl_xor_sync(0xffffffffu, rsA, 1);
        rsA += __shfl_xor_sync(0xffffffffu, rsA, 2);
        rsB += __shfl_xor_sync(0xffffffffu, rsB, 1);
        rsB += __shfl_xor_sync(0xffffffffu, rsB, 2);
        lA = lA * corrA + rsA;
        lB = lB * corrB + rsB;
#pragma unroll
        for (int n = 0; n < 8; n++) {
            o[n][0] *= corrA; o[n][1] *= corrA;
            o[n][2] *= corrB; o[n][3] *= corrB;
        }

        // ---- O += P V (3-term). P frags from registers; V via ldmatrix.trans
#pragma unroll
        for (int kt2 = 0; kt2 < 4; kt2++) {
            uint32_t ah[4] = {ph[2 * kt2][0], ph[2 * kt2][1],
                              ph[2 * kt2 + 1][0], ph[2 * kt2 + 1][1]};
            uint32_t al[4] = {pl[2 * kt2][0], pl[2 * kt2][1],
                              pl[2 * kt2 + 1][0], pl[2 * kt2 + 1][1]};
#pragma unroll
            for (int np = 0; np < 4; np++) {
                uint32_t base = kt2 * (16 * AROWB) + np * 32 + qoff;
                uint32_t vh4[4], vl4[4];
                ldmatrix_x4t(vh4, Vhb + base);
                ldmatrix_x4t(vl4, Vlb + base);
                mma16816(o[2 * np],     ah, vh4);
                mma16816(o[2 * np + 1], ah, vh4 + 2);
                mma16816(o[2 * np],     ah, vl4);
                mma16816(o[2 * np + 1], ah, vl4 + 2);
                mma16816(o[2 * np],     al, vh4);
                mma16816(o[2 * np + 1], al, vh4 + 2);
            }
        }
    }

    // ---- Epilogue: normalize, split, store oh/ol [M][1024]
    float invA = 1.0f / lA, invB = 1.0f / lB;
    int g = lane >> 2, ec = (lane & 3) * 2;
    size_t rowA = qrow0 + w * 16 + g;
    size_t rowB = rowA + 8;
#pragma unroll
    for (int n = 0; n < 8; n++) {
        size_t col = hc + n * 8 + ec;
        float v0 = o[n][0] * invA, v1 = o[n][1] * invA;
        float v2 = o[n][2] * invB, v3 = o[n][3] * invB;
        __nv_bfloat16 h0, l0, h1, l1, h2, l2, h3, l3;
        bf16split(v0, h0, l0); bf16split(v1, h1, l1);
        bf16split(v2, h2, l2); bf16split(v3, h3, l3);
        *(__nv_bfloat162*)(Ohi + rowA * 1024 + col) = __nv_bfloat162(h0, h1);
        *(__nv_bfloat162*)(Olo + rowA * 1024 + col) = __nv_bfloat162(l0, l1);
        *(__nv_bfloat162*)(Ohi + rowB * 1024 + col) = __nv_bfloat162(h2, h3);
        *(__nv_bfloat162*)(Olo + rowB * 1024 + col) = __nv_bfloat162(l2, l3);
    }
}

// ===========================================================================
extern "C" void kernel_launch(void* const* d_in, const int* in_sizes, int n_in,
                              void* d_out, int out_size) {
    const float* x  = (const float*)d_in[0];
    const float* Wq = (const float*)d_in[1];
    const float* Wk = (const float*)d_in[2];
    const float* Wv = (const float*)d_in[3];
    const float* Wo = (const float*)d_in[4];
    float* out = (float*)d_out;

    __nv_bfloat16 *qh, *ql, *kh, *kl, *vh, *vl, *oh, *ol, *xh, *xl, *wth, *wtl;
    cudaGetSymbolAddress((void**)&qh, g_qh);
    cudaGetSymbolAddress((void**)&ql, g_ql);
    cudaGetSymbolAddress((void**)&kh, g_kh);
    cudaGetSymbolAddress((void**)&kl, g_kl);
    cudaGetSymbolAddress((void**)&vh, g_vh);
    cudaGetSymbolAddress((void**)&vl, g_vl);
    cudaGetSymbolAddress((void**)&oh, g_oh);
    cudaGetSymbolAddress((void**)&ol, g_ol);
    cudaGetSymbolAddress((void**)&xh, g_xh);
    cudaGetSymbolAddress((void**)&xl, g_xl);
    cudaGetSymbolAddress((void**)&wth, g_wth);
    cudaGetSymbolAddress((void**)&wtl, g_wtl);

    cudaFuncSetAttribute(gemm_mma_kernel,
                         cudaFuncAttributeMaxDynamicSharedMemorySize, GEMM_SMEM_BYTES);
    cudaFuncSetAttribute(attn_mma_kernel,
                         cudaFuncAttributeMaxDynamicSharedMemorySize, ATT_SMEM_BYTES);

    // 1. Split x into bf16 hi/lo
    split_kernel<<<(M_ * D_ / 4 + 255) / 256, 256>>>(x, xh, xl, M_ * D_ / 4);

    // 2. Transpose + split weights -> [n][k] bf16
    tsplit_kernel<<<dim3(32, 32, 4), 256>>>(Wq, Wk, Wv, Wo, wth, wtl);

    // 3. QKV projections -> pre-split bf16 hi/lo (q scaled by QSCALE)
    gemm_mma_kernel<<<dim3(8, 32, 3), 256, GEMM_SMEM_BYTES>>>(
        xh, xl, wth, wtl, qh, ql, kh, kl, vh, vl, nullptr, QSCALE);

    // 4. Tensor-core flash attention -> pre-split oh/ol
    attn_mma_kernel<<<dim3(16, 16, 2), 256, ATT_SMEM_BYTES>>>(
        qh, ql, kh, kl, vh, vl, oh, ol);

    // 5. Output projection -> fp32 d_out
    gemm_mma_kernel<<<dim3(8, 32, 1), 256, GEMM_SMEM_BYTES>>>(
        oh, ol, wth + (size_t)3 * D_ * N_, wtl + (size_t)3 * D_ * N_,
        nullptr, nullptr, nullptr, nullptr, nullptr, nullptr, out, 1.0f);
}

// round 13
// speedup vs baseline: 3.8450x; 1.9393x over previous
#include <cuda_runtime.h>
#include <cuda_bf16.h>
#include <cstdint>
#include <math.h>

// Problem constants
#define B_  2
#define S_  2048
#define D_  1024
#define H_  16
#define C_  64
#define M_  (B_ * S_)      // 4096
#define N_  (H_ * C_)      // 1024

#define QSCALE 0.18033688011112042f   // C^-0.5 * log2(e)

// Scratch (device globals: allocation-free rule)
__device__ __nv_bfloat16 g_qh[M_ * N_], g_ql[M_ * N_];
__device__ __nv_bfloat16 g_kh[M_ * N_], g_kl[M_ * N_];
__device__ __nv_bfloat16 g_vh[M_ * N_], g_vl[M_ * N_];
__device__ __nv_bfloat16 g_oh[M_ * N_], g_ol[M_ * N_];
__device__ __nv_bfloat16 g_xh[M_ * D_], g_xl[M_ * D_];
__device__ __nv_bfloat16 g_wth[4 * D_ * N_], g_wtl[4 * D_ * N_];  // W^T [n][k]

// ===========================================================================
// Base-ISA PTX helpers (validated on this toolchain in R9/R12)
// ===========================================================================
__device__ __forceinline__ uint32_t smem_u32(const void* p) {
    uint32_t a;
    asm("{ .reg .u64 t; cvta.to.shared.u64 t, %1; cvt.u32.u64 %0, t; }"
        : "=r"(a) : "l"(p));
    return a;
}
__device__ __forceinline__ void ldmatrix_x4(uint32_t* r, uint32_t addr) {
    asm volatile("ldmatrix.sync.aligned.m8n8.x4.shared.b16 {%0,%1,%2,%3}, [%4];"
                 : "=r"(r[0]), "=r"(r[1]), "=r"(r[2]), "=r"(r[3]) : "r"(addr));
}
__device__ __forceinline__ void ldmatrix_x4t(uint32_t* r, uint32_t addr) {
    asm volatile("ldmatrix.sync.aligned.m8n8.x4.trans.shared.b16 {%0,%1,%2,%3}, [%4];"
                 : "=r"(r[0]), "=r"(r[1]), "=r"(r[2]), "=r"(r[3]) : "r"(addr));
}
__device__ __forceinline__ void mma16816(float* d, const uint32_t* a, const uint32_t* b) {
    asm volatile(
        "mma.sync.aligned.m16n8k16.row.col.f32.bf16.bf16.f32 "
        "{%0,%1,%2,%3}, {%4,%5,%6,%7}, {%8,%9}, {%0,%1,%2,%3};"
        : "+f"(d[0]), "+f"(d[1]), "+f"(d[2]), "+f"(d[3])
        : "r"(a[0]), "r"(a[1]), "r"(a[2]), "r"(a[3]), "r"(b[0]), "r"(b[1]));
}
__device__ __forceinline__ void cp_async16(uint32_t saddr, const void* gaddr) {
    asm volatile("cp.async.cg.shared.global [%0], [%1], 16;"
                 :: "r"(saddr), "l"(gaddr));
}
#define CP_COMMIT() asm volatile("cp.async.commit_group;" ::: "memory")
#define CP_WAIT(N)  asm volatile("cp.async.wait_group %0;" :: "n"(N) : "memory")

__device__ __forceinline__ uint32_t packbf2(float a, float b) {
    __nv_bfloat162 t(__float2bfloat16_rn(a), __float2bfloat16_rn(b));
    return *(uint32_t*)&t;
}

// Fast exp2 on the FMA pipe. Valid for x <= 0. Max rel err ~1.5e-7.
__device__ __forceinline__ float fexp2(float x) {
    x = fmaxf(x, -110.0f);
    float r = rintf(x);
    float f = x - r;
    float p =            1.5403530e-4f;
    p = fmaf(p, f,       1.3333558e-3f);
    p = fmaf(p, f,       9.6181291e-3f);
    p = fmaf(p, f,       5.5504109e-2f);
    p = fmaf(p, f,       2.4022651e-1f);
    p = fmaf(p, f,       6.9314718e-1f);
    p = fmaf(p, f,       1.0f);
    return __int_as_float(__float_as_int(p) + (((int)r) << 23));
}

// ===========================================================================
// fp32 -> (bf16 hi, bf16 lo) split kernels
// ===========================================================================
__device__ __forceinline__ void bf16split(float v, __nv_bfloat16& h, __nv_bfloat16& l) {
    h = __float2bfloat16_rn(v);
    l = __float2bfloat16_rn(v - __bfloat162float(h));
}

__global__ __launch_bounds__(256)
void split_kernel(const float* __restrict__ in, __nv_bfloat16* __restrict__ hi,
                  __nv_bfloat16* __restrict__ lo, int n4) {
    int i = blockIdx.x * 256 + threadIdx.x;
    if (i >= n4) return;
    float4 v = ((const float4*)in)[i];
    __nv_bfloat16 h0, l0, h1, l1, h2, l2, h3, l3;
    bf16split(v.x, h0, l0); bf16split(v.y, h1, l1);
    bf16split(v.z, h2, l2); bf16split(v.w, h3, l3);
    ((__nv_bfloat162*)hi)[2 * i]     = __nv_bfloat162(h0, h1);
    ((__nv_bfloat162*)hi)[2 * i + 1] = __nv_bfloat162(h2, h3);
    ((__nv_bfloat162*)lo)[2 * i]     = __nv_bfloat162(l0, l1);
    ((__nv_bfloat162*)lo)[2 * i + 1] = __nv_bfloat162(l2, l3);
}

__global__ __launch_bounds__(256)
void tsplit_kernel(const float* __restrict__ W0, const float* __restrict__ W1,
                   const float* __restrict__ W2, const float* __restrict__ W3,
                   __nv_bfloat16* __restrict__ oh, __nv_bfloat16* __restrict__ ol) {
    int z = blockIdx.z;
    const float* W = (z == 0) ? W0 : (z == 1) ? W1 : (z == 2) ? W2 : W3;
    __nv_bfloat16* outh = oh + (size_t)z * D_ * N_;
    __nv_bfloat16* outl = ol + (size_t)z * D_ * N_;
    __shared__ float t[32][33];
    int tx = threadIdx.x & 31, ty = threadIdx.x >> 5;
    int k0 = blockIdx.y * 32, n0 = blockIdx.x * 32;
#pragma unroll
    for (int i = 0; i < 32; i += 8)
        t[ty + i][tx] = W[(size_t)(k0 + ty + i) * 1024 + n0 + tx];
    __syncthreads();
#pragma unroll
    for (int i = 0; i < 32; i += 8) {
        float v = t[tx][ty + i];
        __nv_bfloat16 h, l;
        bf16split(v, h, l);
        size_t o = (size_t)(n0 + ty + i) * 1024 + k0 + tx;
        outh[o] = h;
        outl[o] = l;
    }
}

// ===========================================================================
// mma.sync GEMM (R9-validated core). 3-term split, CTA 128x128, BK=64.
// __launch_bounds__(256,2): force 2 CTAs/SM (was reg-limited to 1).
// ===========================================================================
#define GSTRIDE 72
#define GE_AH 0
#define GE_AL (128 * GSTRIDE)
#define GE_BH (2 * 128 * GSTRIDE)
#define GE_BL (3 * 128 * GSTRIDE)
#define GEMM_SMEM_BYTES (4 * 128 * GSTRIDE * 2)   // 73728 B

__global__ __launch_bounds__(256, 2)
void gemm_mma_kernel(const __nv_bfloat16* __restrict__ Ah,
                     const __nv_bfloat16* __restrict__ Al,
                     const __nv_bfloat16* __restrict__ Bth,
                     const __nv_bfloat16* __restrict__ Btl,
                     __nv_bfloat16* __restrict__ Oh0, __nv_bfloat16* __restrict__ Ol0,
                     __nv_bfloat16* __restrict__ Oh1, __nv_bfloat16* __restrict__ Ol1,
                     __nv_bfloat16* __restrict__ Oh2, __nv_bfloat16* __restrict__ Ol2,
                     float* __restrict__ Cf, float alpha0) {
    extern __shared__ __nv_bfloat16 smg[];
    const uint32_t sbase = smem_u32(smg);

    int tid = threadIdx.x;
    int wid = tid >> 5, lane = tid & 31;
    int warp_m = (wid & 3) * 32;
    int warp_n = (wid >> 2) * 64;

    int z = blockIdx.z;
    const __nv_bfloat16* Bh = Bth + (size_t)z * D_ * N_;
    const __nv_bfloat16* Bl = Btl + (size_t)z * D_ * N_;
    __nv_bfloat16* Oh = (z == 0) ? Oh0 : (z == 1) ? Oh1 : Oh2;
    __nv_bfloat16* Ol = (z == 0) ? Ol0 : (z == 1) ? Ol1 : Ol2;
    float alpha = (z == 0) ? alpha0 : 1.0f;

    const size_t arow0 = (size_t)blockIdx.y * 128;
    const size_t brow0 = (size_t)blockIdx.x * 128;

    float d[2][8][4];
#pragma unroll
    for (int t = 0; t < 2; t++)
#pragma unroll
        for (int j = 0; j < 8; j++)
#pragma unroll
            for (int e = 0; e < 4; e++) d[t][j][e] = 0.0f;

    int a_row = lane & 15;
    int a_col = (lane >> 4) * 8;
    int b_loc = lane & 7;
    int b_mat = lane >> 3;
    int b_rowoff = (b_mat >> 1) * 8 + b_loc;
    int b_coloff = (b_mat & 1) * 8;

    for (int k0 = 0; k0 < 1024; k0 += 64) {
        __syncthreads();
        for (int i = tid; i < 1024; i += 256) {
            int row = i >> 3;
            int c8  = (i & 7) * 8;
            size_t ga = (arow0 + row) * 1024 + k0 + c8;
            size_t gb = (brow0 + row) * 1024 + k0 + c8;
            int so = row * GSTRIDE + c8;
            *(uint4*)(smg + GE_AH + so) = *(const uint4*)(Ah + ga);
            *(uint4*)(smg + GE_AL + so) = *(const uint4*)(Al + ga);
            *(uint4*)(smg + GE_BH + so) = *(const uint4*)(Bh + gb);
            *(uint4*)(smg + GE_BL + so) = *(const uint4*)(Bl + gb);
        }
        __syncthreads();

#pragma unroll
        for (int kk = 0; kk < 64; kk += 16) {
            uint32_t aH[2][4], aL[2][4];
#pragma unroll
            for (int t = 0; t < 2; t++) {
                int off = (warp_m + t * 16 + a_row) * GSTRIDE + kk + a_col;
                ldmatrix_x4(aH[t], sbase + (GE_AH + off) * 2);
                ldmatrix_x4(aL[t], sbase + (GE_AL + off) * 2);
            }
            uint32_t bH[8][2], bL[8][2];
#pragma unroll
            for (int jj = 0; jj < 8; jj += 2) {
                int off = (warp_n + jj * 8 + b_rowoff) * GSTRIDE + kk + b_coloff;
                uint32_t r[4];
                ldmatrix_x4(r, sbase + (GE_BH + off) * 2);
                bH[jj][0] = r[0]; bH[jj][1] = r[1];
                bH[jj + 1][0] = r[2]; bH[jj + 1][1] = r[3];
                ldmatrix_x4(r, sbase + (GE_BL + off) * 2);
                bL[jj][0] = r[0]; bL[jj][1] = r[1];
                bL[jj + 1][0] = r[2]; bL[jj + 1][1] = r[3];
            }
#pragma unroll
            for (int t = 0; t < 2; t++)
#pragma unroll
                for (int j = 0; j < 8; j++) {
                    mma16816(d[t][j], aH[t], bH[j]);
                    mma16816(d[t][j], aH[t], bL[j]);
                    mma16816(d[t][j], aL[t], bH[j]);
                }
        }
    }

    int er = lane >> 2;
    int ec = (lane & 3) * 2;
#pragma unroll
    for (int t = 0; t < 2; t++)
#pragma unroll
        for (int j = 0; j < 8; j++) {
            size_t row = arow0 + warp_m + t * 16 + er;
            size_t col = brow0 + warp_n + j * 8 + ec;
            float v0 = alpha * d[t][j][0], v1 = alpha * d[t][j][1];
            float v2 = alpha * d[t][j][2], v3 = alpha * d[t][j][3];
            if (Cf) {
                *(float2*)(Cf + row * 1024 + col)       = make_float2(v0, v1);
                *(float2*)(Cf + (row + 8) * 1024 + col) = make_float2(v2, v3);
            } else {
                __nv_bfloat16 h0, l0, h1, l1, h2, l2, h3, l3;
                bf16split(v0, h0, l0); bf16split(v1, h1, l1);
                bf16split(v2, h2, l2); bf16split(v3, h3, l3);
                *(__nv_bfloat162*)(Oh + row * 1024 + col)       = __nv_bfloat162(h0, h1);
                *(__nv_bfloat162*)(Ol + row * 1024 + col)       = __nv_bfloat162(l0, l1);
                *(__nv_bfloat162*)(Oh + (row + 8) * 1024 + col) = __nv_bfloat162(h2, h3);
                *(__nv_bfloat162*)(Ol + (row + 8) * 1024 + col) = __nv_bfloat162(l2, l3);
            }
        }
}

// ===========================================================================
// Tensor-core flash attention. R12 core, resized for occupancy:
// Block = (qt, h, b): 64 queries, 4 warps x 16 rows, 128 threads.
// regs 154x128=19.7K, smem 73.7KB -> 3 CTAs/SM (was 1) = 3x latency hiding.
// ===========================================================================
#define AROWB 144                      // 72 bf16 per smem row
#define STAGE_BYTES (4 * 64 * AROWB)   // Kh,Kl,Vh,Vl tiles: 36864 B
#define ATT_SMEM_BYTES (2 * STAGE_BYTES)
#define QTILE 64
#define ATH 128                        // attn threads

__global__ __launch_bounds__(ATH, 3)
void attn_mma_kernel(const __nv_bfloat16* __restrict__ Qh, const __nv_bfloat16* __restrict__ Ql,
                     const __nv_bfloat16* __restrict__ Kh, const __nv_bfloat16* __restrict__ Kl,
                     const __nv_bfloat16* __restrict__ Vh, const __nv_bfloat16* __restrict__ Vl,
                     __nv_bfloat16* __restrict__ Ohi, __nv_bfloat16* __restrict__ Olo) {
    extern __shared__ char sm[];
    const uint32_t sb = smem_u32(sm);

    int tid = threadIdx.x;
    int w = tid >> 5, lane = tid & 31;
    int qt = blockIdx.x, h = blockIdx.y, b = blockIdx.z;

    const size_t qrow0 = (size_t)(b * S_ + qt * QTILE);
    const size_t krow0 = (size_t)(b * S_);
    const int    hc    = h * 64;

    // ---- Stage Q (bf16 hi/lo) into stage-0: Qh [64][72] @0, Ql @9216
#pragma unroll
    for (int t = 0; t < 8; t++) {
        int a   = t >> 2;                    // 0: Qh, 1: Ql
        int rem = (t & 3) * ATH + tid;       // 0..511
        int row = rem >> 3, ch = rem & 7;
        const __nv_bfloat16* src = a ? Ql : Qh;
        cp_async16(sb + a * 9216 + row * AROWB + ch * 16,
                   src + (qrow0 + row) * 1024 + hc + ch * 8);
    }
    CP_COMMIT();
    CP_WAIT(0);
    __syncthreads();

    // ---- Q fragments to registers (held for whole kernel)
    int li = lane & 7, lt = lane >> 3;
    int qoff = ((lt & 1) * 8 + li) * AROWB + (lt >> 1) * 16;   // A-frag / trans-B addressing
    int koff = ((lt >> 1) * 8 + li) * AROWB + (lt & 1) * 16;   // B-frag addressing
    uint32_t qfh[4][4], qfl[4][4];
#pragma unroll
    for (int kk = 0; kk < 4; kk++) {
        ldmatrix_x4(qfh[kk], sb +        w * (16 * AROWB) + kk * 32 + qoff);
        ldmatrix_x4(qfl[kk], sb + 9216 + w * (16 * AROWB) + kk * 32 + qoff);
    }
    __syncthreads();   // stage-0 free for K/V

    // ---- Prefetch key tile 0 -> stage 0 (Kh,Kl,Vh,Vl: 4 x [64][72])
#pragma unroll
    for (int t = 0; t < 16; t++) {
        int a = t >> 2;
        int rem = (t & 3) * ATH + tid;
        int row = rem >> 3, ch = rem & 7;
        const __nv_bfloat16* src = (a == 0) ? Kh : (a == 1) ? Kl : (a == 2) ? Vh : Vl;
        cp_async16(sb + a * 9216 + row * AROWB + ch * 16,
                   src + (krow0 + row) * 1024 + hc + ch * 8);
    }
    CP_COMMIT();

    float o[8][4];
#pragma unroll
    for (int n = 0; n < 8; n++)
#pragma unroll
        for (int e = 0; e < 4; e++) o[n][e] = 0.0f;
    float mA = -1e30f, mB = -1e30f, lA = 0.0f, lB = 0.0f;

    for (int kt = 0; kt < 32; kt++) {
        int cur = kt & 1;
        __syncthreads();
        if (kt + 1 < 32) {
            uint32_t nsb = sb + ((kt + 1) & 1) * STAGE_BYTES;
            size_t krow = krow0 + (size_t)(kt + 1) * 64;
#pragma unroll
            for (int t = 0; t < 16; t++) {
                int a = t >> 2;
                int rem = (t & 3) * ATH + tid;
                int row = rem >> 3, ch = rem & 7;
                const __nv_bfloat16* src = (a == 0) ? Kh : (a == 1) ? Kl : (a == 2) ? Vh : Vl;
                cp_async16(nsb + a * 9216 + row * AROWB + ch * 16,
                           src + (krow + row) * 1024 + hc + ch * 8);
            }
        }
        CP_COMMIT();
        CP_WAIT(1);        // current tile resident (groups retire in order)
        __syncthreads();

        uint32_t Kb  = sb + cur * STAGE_BYTES;
        uint32_t Klb = Kb + 9216, Vhb = Kb + 18432, Vlb = Kb + 27648;

        // ---- S = Q K^T (3-term). s[j]: n-tile j = keys 8j..8j+7
        float s[8][4];
#pragma unroll
        for (int j = 0; j < 8; j++)
#pragma unroll
            for (int e = 0; e < 4; e++) s[j][e] = 0.0f;

#pragma unroll
        for (int kk = 0; kk < 4; kk++)
#pragma unroll
            for (int jp = 0; jp < 4; jp++) {
                uint32_t base = jp * (16 * AROWB) + kk * 32 + koff;
                uint32_t kh4[4], kl4[4];
                ldmatrix_x4(kh4, Kb + base);
                ldmatrix_x4(kl4, Klb + base);
                mma16816(s[2 * jp],     qfh[kk], kh4);
                mma16816(s[2 * jp + 1], qfh[kk], kh4 + 2);
                mma16816(s[2 * jp],     qfh[kk], kl4);
                mma16816(s[2 * jp + 1], qfh[kk], kl4 + 2);
                mma16816(s[2 * jp],     qfl[kk], kh4);
                mma16816(s[2 * jp + 1], qfl[kk], kh4 + 2);
            }

        // ---- Online softmax (rows g = lane>>2 and g+8)
        float mxA = -1e30f, mxB = -1e30f;
#pragma unroll
        for (int j = 0; j < 8; j++) {
            mxA = fmaxf(mxA, fmaxf(s[j][0], s[j][1]));
            mxB = fmaxf(mxB, fmaxf(s[j][2], s[j][3]));
        }
        mxA = fmaxf(mxA, __shfl_xor_sync(0xffffffffu, mxA, 1));
        mxA = fmaxf(mxA, __shfl_xor_sync(0xffffffffu, mxA, 2));
        mxB = fmaxf(mxB, __shfl_xor_sync(0xffffffffu, mxB, 1));
        mxB = fmaxf(mxB, __shfl_xor_sync(0xffffffffu, mxB, 2));
        float mnA = fmaxf(mA, mxA), mnB = fmaxf(mB, mxB);
        float corrA = fexp2(mA - mnA), corrB = fexp2(mB - mnB);
        mA = mnA; mB = mnB;

        float rsA = 0.0f, rsB = 0.0f;
        uint32_t ph[8][2], pl[8][2];
#pragma unroll
        for (int j = 0; j < 8; j++) {
            float p0 = fexp2(s[j][0] - mnA);
            float p1 = fexp2(s[j][1] - mnA);
            float p2 = fexp2(s[j][2] - mnB);
            float p3 = fexp2(s[j][3] - mnB);
            rsA += p0 + p1;
            rsB += p2 + p3;
            __nv_bfloat16 h0 = __float2bfloat16_rn(p0), h1 = __float2bfloat16_rn(p1);
            __nv_bfloat16 h2 = __float2bfloat16_rn(p2), h3 = __float2bfloat16_rn(p3);
            ph[j][0] = packbf2(p0, p1);
            ph[j][1] = packbf2(p2, p3);
            pl[j][0] = packbf2(p0 - __bfloat162float(h0), p1 - __bfloat162float(h1));
            pl[j][1] = packbf2(p2 - __bfloat162float(h2), p3 - __bfloat162float(h3));
        }
        rsA += __shfl_xor_sync(0xffffffffu, rsA, 1);
        rsA += __shfl_xor_sync(0xffffffffu, rsA, 2);
        rsB += __shfl_xor_sync(0xffffffffu, rsB, 1);
        rsB += __shfl_xor_sync(0xffffffffu, rsB, 2);
        lA = lA * corrA + rsA;
        lB = lB * corrB + rsB;
#pragma unroll
        for (int n = 0; n < 8; n++) {
            o[n][0] *= corrA; o[n][1] *= corrA;
            o[n][2] *= corrB; o[n][3] *= corrB;
        }

        // ---- O += P V (3-term). P frags from registers; V via ldmatrix.trans
#pragma unroll
        for (int kt2 = 0; kt2 < 4; kt2++) {
            uint32_t ah[4] = {ph[2 * kt2][0], ph[2 * kt2][1],
                              ph[2 * kt2 + 1][0], ph[2 * kt2 + 1][1]};
            uint32_t al[4] = {pl[2 * kt2][0], pl[2 * kt2][1],
                              pl[2 * kt2 + 1][0], pl[2 * kt2 + 1][1]};
#pragma unroll
            for (int np = 0; np < 4; np++) {
                uint32_t base = kt2 * (16 * AROWB) + np * 32 + qoff;
                uint32_t vh4[4], vl4[4];
                ldmatrix_x4t(vh4, Vhb + base);
                ldmatrix_x4t(vl4, Vlb + base);
                mma16816(o[2 * np],     ah, vh4);
                mma16816(o[2 * np + 1], ah, vh4 + 2);
                mma16816(o[2 * np],     ah, vl4);
                mma16816(o[2 * np + 1], ah, vl4 + 2);
                mma16816(o[2 * np],     al, vh4);
                mma16816(o[2 * np + 1], al, vh4 + 2);
            }
        }
    }

    // ---- Epilogue: normalize, split, store oh/ol [M][1024]
    float invA = 1.0f / lA, invB = 1.0f / lB;
    int g = lane >> 2, ec = (lane & 3) * 2;
    size_t rowA = qrow0 + w * 16 + g;
    size_t rowB = rowA + 8;
#pragma unroll
    for (int n = 0; n < 8; n++) {
        size_t col = hc + n * 8 + ec;
        float v0 = o[n][0] * invA, v1 = o[n][1] * invA;
        float v2 = o[n][2] * invB, v3 = o[n][3] * invB;
        __nv_bfloat16 h0, l0, h1, l1, h2, l2, h3, l3;
        bf16split(v0, h0, l0); bf16split(v1, h1, l1);
        bf16split(v2, h2, l2); bf16split(v3, h3, l3);
        *(__nv_bfloat162*)(Ohi + rowA * 1024 + col) = __nv_bfloat162(h0, h1);
        *(__nv_bfloat162*)(Olo + rowA * 1024 + col) = __nv_bfloat162(l0, l1);
        *(__nv_bfloat162*)(Ohi + rowB * 1024 + col) = __nv_bfloat162(h2, h3);
        *(__nv_bfloat162*)(Olo + rowB * 1024 + col) = __nv_bfloat162(l2, l3);
    }
}

// ===========================================================================
extern "C" void kernel_launch(void* const* d_in, const int* in_sizes, int n_in,
                              void* d_out, int out_size) {
    const float* x  = (const float*)d_in[0];
    const float* Wq = (const float*)d_in[1];
    const float* Wk = (const float*)d_in[2];
    const float* Wv = (const float*)d_in[3];
    const float* Wo = (const float*)d_in[4];
    float* out = (float*)d_out;

    __nv_bfloat16 *qh, *ql, *kh, *kl, *vh, *vl, *oh, *ol, *xh, *xl, *wth, *wtl;
    cudaGetSymbolAddress((void**)&qh, g_qh);
    cudaGetSymbolAddress((void**)&ql, g_ql);
    cudaGetSymbolAddress((void**)&kh, g_kh);
    cudaGetSymbolAddress((void**)&kl, g_kl);
    cudaGetSymbolAddress((void**)&vh, g_vh);
    cudaGetSymbolAddress((void**)&vl, g_vl);
    cudaGetSymbolAddress((void**)&oh, g_oh);
    cudaGetSymbolAddress((void**)&ol, g_ol);
    cudaGetSymbolAddress((void**)&xh, g_xh);
    cudaGetSymbolAddress((void**)&xl, g_xl);
    cudaGetSymbolAddress((void**)&wth, g_wth);
    cudaGetSymbolAddress((void**)&wtl, g_wtl);

    cudaFuncSetAttribute(gemm_mma_kernel,
                         cudaFuncAttributeMaxDynamicSharedMemorySize, GEMM_SMEM_BYTES);
    cudaFuncSetAttribute(attn_mma_kernel,
                         cudaFuncAttributeMaxDynamicSharedMemorySize, ATT_SMEM_BYTES);

    // 1. Split x into bf16 hi/lo
    split_kernel<<<(M_ * D_ / 4 + 255) / 256, 256>>>(x, xh, xl, M_ * D_ / 4);

    // 2. Transpose + split weights -> [n][k] bf16
    tsplit_kernel<<<dim3(32, 32, 4), 256>>>(Wq, Wk, Wv, Wo, wth, wtl);

    // 3. QKV projections -> pre-split bf16 hi/lo (q scaled by QSCALE)
    gemm_mma_kernel<<<dim3(8, 32, 3), 256, GEMM_SMEM_BYTES>>>(
        xh, xl, wth, wtl, qh, ql, kh, kl, vh, vl, nullptr, QSCALE);

    // 4. Tensor-core flash attention (64-query CTAs, 3/SM) -> pre-split oh/ol
    attn_mma_kernel<<<dim3(S_ / QTILE, 16, 2), ATH, ATT_SMEM_BYTES>>>(
        qh, ql, kh, kl, vh, vl, oh, ol);

    // 5. Output projection -> fp32 d_out
    gemm_mma_kernel<<<dim3(8, 32, 1), 256, GEMM_SMEM_BYTES>>>(
        oh, ol, wth + (size_t)3 * D_ * N_, wtl + (size_t)3 * D_ * N_,
        nullptr, nullptr, nullptr, nullptr, nullptr, nullptr, out, 1.0f);
}

// round 17
// speedup vs baseline: 5.8687x; 1.5263x over previous
#include <cuda_runtime.h>
#include <cuda_bf16.h>
#include <cuda_fp16.h>
#include <cstdint>
#include <math.h>

// Problem constants
#define B_  2
#define S_  2048
#define D_  1024
#define H_  16
#define C_  64
#define M_  (B_ * S_)      // 4096
#define N_  (H_ * C_)      // 1024

#define QSCALE 0.18033688011112042f   // C^-0.5 * log2(e)

// Scratch (device globals: allocation-free rule)
__device__ __half        g_qf[M_ * N_], g_kf[M_ * N_], g_vf[M_ * N_];
__device__ __nv_bfloat16 g_oh[M_ * N_], g_ol[M_ * N_];
__device__ __nv_bfloat16 g_xh[M_ * D_], g_xl[M_ * D_];
__device__ __nv_bfloat16 g_wth[4 * D_ * N_], g_wtl[4 * D_ * N_];  // W^T [n][k]

// ===========================================================================
// Base-ISA PTX helpers (validated on this toolchain in R9/R12/R13)
// ===========================================================================
__device__ __forceinline__ uint32_t smem_u32(const void* p) {
    uint32_t a;
    asm("{ .reg .u64 t; cvta.to.shared.u64 t, %1; cvt.u32.u64 %0, t; }"
        : "=r"(a) : "l"(p));
    return a;
}
__device__ __forceinline__ void ldmatrix_x4(uint32_t* r, uint32_t addr) {
    asm volatile("ldmatrix.sync.aligned.m8n8.x4.shared.b16 {%0,%1,%2,%3}, [%4];"
                 : "=r"(r[0]), "=r"(r[1]), "=r"(r[2]), "=r"(r[3]) : "r"(addr));
}
__device__ __forceinline__ void ldmatrix_x4t(uint32_t* r, uint32_t addr) {
    asm volatile("ldmatrix.sync.aligned.m8n8.x4.trans.shared.b16 {%0,%1,%2,%3}, [%4];"
                 : "=r"(r[0]), "=r"(r[1]), "=r"(r[2]), "=r"(r[3]) : "r"(addr));
}
__device__ __forceinline__ void mma16816(float* d, const uint32_t* a, const uint32_t* b) {
    asm volatile(
        "mma.sync.aligned.m16n8k16.row.col.f32.bf16.bf16.f32 "
        "{%0,%1,%2,%3}, {%4,%5,%6,%7}, {%8,%9}, {%0,%1,%2,%3};"
        : "+f"(d[0]), "+f"(d[1]), "+f"(d[2]), "+f"(d[3])
        : "r"(a[0]), "r"(a[1]), "r"(a[2]), "r"(a[3]), "r"(b[0]), "r"(b[1]));
}
// fp16 variant: identical shape/throughput, 8x less quantization error than bf16
__device__ __forceinline__ void mma16816h(float* d, const uint32_t* a, const uint32_t* b) {
    asm volatile(
        "mma.sync.aligned.m16n8k16.row.col.f32.f16.f16.f32 "
        "{%0,%1,%2,%3}, {%4,%5,%6,%7}, {%8,%9}, {%0,%1,%2,%3};"
        : "+f"(d[0]), "+f"(d[1]), "+f"(d[2]), "+f"(d[3])
        : "r"(a[0]), "r"(a[1]), "r"(a[2]), "r"(a[3]), "r"(b[0]), "r"(b[1]));
}
__device__ __forceinline__ void cp_async16(uint32_t saddr, const void* gaddr) {
    asm volatile("cp.async.cg.shared.global [%0], [%1], 16;"
                 :: "r"(saddr), "l"(gaddr));
}
#define CP_COMMIT() asm volatile("cp.async.commit_group;" ::: "memory")
#define CP_WAIT(N)  asm volatile("cp.async.wait_group %0;" :: "n"(N) : "memory")

__device__ __forceinline__ uint32_t packhf2(float a, float b) {
    __half2 t = __floats2half2_rn(a, b);
    return *(uint32_t*)&t;
}

// Fast exp2 on the FMA pipe. Valid for x <= 0. Max rel err ~1.5e-7.
__device__ __forceinline__ float fexp2(float x) {
    x = fmaxf(x, -110.0f);
    float r = rintf(x);
    float f = x - r;
    float p =            1.5403530e-4f;
    p = fmaf(p, f,       1.3333558e-3f);
    p = fmaf(p, f,       9.6181291e-3f);
    p = fmaf(p, f,       5.5504109e-2f);
    p = fmaf(p, f,       2.4022651e-1f);
    p = fmaf(p, f,       6.9314718e-1f);
    p = fmaf(p, f,       1.0f);
    return __int_as_float(__float_as_int(p) + (((int)r) << 23));
}

// ===========================================================================
// fp32 -> (bf16 hi, bf16 lo) split kernels
// ===========================================================================
__device__ __forceinline__ void bf16split(float v, __nv_bfloat16& h, __nv_bfloat16& l) {
    h = __float2bfloat16_rn(v);
    l = __float2bfloat16_rn(v - __bfloat162float(h));
}

__global__ __launch_bounds__(256)
void split_kernel(const float* __restrict__ in, __nv_bfloat16* __restrict__ hi,
                  __nv_bfloat16* __restrict__ lo, int n4) {
    int i = blockIdx.x * 256 + threadIdx.x;
    if (i >= n4) return;
    float4 v = ((const float4*)in)[i];
    __nv_bfloat16 h0, l0, h1, l1, h2, l2, h3, l3;
    bf16split(v.x, h0, l0); bf16split(v.y, h1, l1);
    bf16split(v.z, h2, l2); bf16split(v.w, h3, l3);
    ((__nv_bfloat162*)hi)[2 * i]     = __nv_bfloat162(h0, h1);
    ((__nv_bfloat162*)hi)[2 * i + 1] = __nv_bfloat162(h2, h3);
    ((__nv_bfloat162*)lo)[2 * i]     = __nv_bfloat162(l0, l1);
    ((__nv_bfloat162*)lo)[2 * i + 1] = __nv_bfloat162(l2, l3);
}

__global__ __launch_bounds__(256)
void tsplit_kernel(const float* __restrict__ W0, const float* __restrict__ W1,
                   const float* __restrict__ W2, const float* __restrict__ W3,
                   __nv_bfloat16* __restrict__ oh, __nv_bfloat16* __restrict__ ol) {
    int z = blockIdx.z;
    const float* W = (z == 0) ? W0 : (z == 1) ? W1 : (z == 2) ? W2 : W3;
    __nv_bfloat16* outh = oh + (size_t)z * D_ * N_;
    __nv_bfloat16* outl = ol + (size_t)z * D_ * N_;
    __shared__ float t[32][33];
    int tx = threadIdx.x & 31, ty = threadIdx.x >> 5;
    int k0 = blockIdx.y * 32, n0 = blockIdx.x * 32;
#pragma unroll
    for (int i = 0; i < 32; i += 8)
        t[ty + i][tx] = W[(size_t)(k0 + ty + i) * 1024 + n0 + tx];
    __syncthreads();
#pragma unroll
    for (int i = 0; i < 32; i += 8) {
        float v = t[tx][ty + i];
        __nv_bfloat16 h, l;
        bf16split(v, h, l);
        size_t o = (size_t)(n0 + ty + i) * 1024 + k0 + tx;
        outh[o] = h;
        outl[o] = l;
    }
}

// ===========================================================================
// mma.sync GEMM (R13-validated core). 3-term bf16 split, CTA 128x128, BK=64.
// Output modes: Cf != null -> fp32 (final projection); else fp16 single
// (q/k/v for the fp16 attention).
// ===========================================================================
#define GSTRIDE 72
#define GE_AH 0
#define GE_AL (128 * GSTRIDE)
#define GE_BH (2 * 128 * GSTRIDE)
#define GE_BL (3 * 128 * GSTRIDE)
#define GEMM_SMEM_BYTES (4 * 128 * GSTRIDE * 2)   // 73728 B

__global__ __launch_bounds__(256, 2)
void gemm_mma_kernel(const __nv_bfloat16* __restrict__ Ah,
                     const __nv_bfloat16* __restrict__ Al,
                     const __nv_bfloat16* __restrict__ Bth,
                     const __nv_bfloat16* __restrict__ Btl,
                     __half* __restrict__ F0, __half* __restrict__ F1,
                     __half* __restrict__ F2,
                     float* __restrict__ Cf, float alpha0) {
    extern __shared__ __nv_bfloat16 smg[];
    const uint32_t sbase = smem_u32(smg);

    int tid = threadIdx.x;
    int wid = tid >> 5, lane = tid & 31;
    int warp_m = (wid & 3) * 32;
    int warp_n = (wid >> 2) * 64;

    int z = blockIdx.z;
    const __nv_bfloat16* Bh = Bth + (size_t)z * D_ * N_;
    const __nv_bfloat16* Bl = Btl + (size_t)z * D_ * N_;
    __half* Fo = (z == 0) ? F0 : (z == 1) ? F1 : F2;
    float alpha = (z == 0) ? alpha0 : 1.0f;

    const size_t arow0 = (size_t)blockIdx.y * 128;
    const size_t brow0 = (size_t)blockIdx.x * 128;

    float d[2][8][4];
#pragma unroll
    for (int t = 0; t < 2; t++)
#pragma unroll
        for (int j = 0; j < 8; j++)
#pragma unroll
            for (int e = 0; e < 4; e++) d[t][j][e] = 0.0f;

    int a_row = lane & 15;
    int a_col = (lane >> 4) * 8;
    int b_loc = lane & 7;
    int b_mat = lane >> 3;
    int b_rowoff = (b_mat >> 1) * 8 + b_loc;
    int b_coloff = (b_mat & 1) * 8;

    for (int k0 = 0; k0 < 1024; k0 += 64) {
        __syncthreads();
        for (int i = tid; i < 1024; i += 256) {
            int row = i >> 3;
            int c8  = (i & 7) * 8;
            size_t ga = (arow0 + row) * 1024 + k0 + c8;
            size_t gb = (brow0 + row) * 1024 + k0 + c8;
            int so = row * GSTRIDE + c8;
            *(uint4*)(smg + GE_AH + so) = *(const uint4*)(Ah + ga);
            *(uint4*)(smg + GE_AL + so) = *(const uint4*)(Al + ga);
            *(uint4*)(smg + GE_BH + so) = *(const uint4*)(Bh + gb);
            *(uint4*)(smg + GE_BL + so) = *(const uint4*)(Bl + gb);
        }
        __syncthreads();

#pragma unroll
        for (int kk = 0; kk < 64; kk += 16) {
            uint32_t aH[2][4], aL[2][4];
#pragma unroll
            for (int t = 0; t < 2; t++) {
                int off = (warp_m + t * 16 + a_row) * GSTRIDE + kk + a_col;
                ldmatrix_x4(aH[t], sbase + (GE_AH + off) * 2);
                ldmatrix_x4(aL[t], sbase + (GE_AL + off) * 2);
            }
            uint32_t bH[8][2], bL[8][2];
#pragma unroll
            for (int jj = 0; jj < 8; jj += 2) {
                int off = (warp_n + jj * 8 + b_rowoff) * GSTRIDE + kk + b_coloff;
                uint32_t r[4];
                ldmatrix_x4(r, sbase + (GE_BH + off) * 2);
                bH[jj][0] = r[0]; bH[jj][1] = r[1];
                bH[jj + 1][0] = r[2]; bH[jj + 1][1] = r[3];
                ldmatrix_x4(r, sbase + (GE_BL + off) * 2);
                bL[jj][0] = r[0]; bL[jj][1] = r[1];
                bL[jj + 1][0] = r[2]; bL[jj + 1][1] = r[3];
            }
#pragma unroll
            for (int t = 0; t < 2; t++)
#pragma unroll
                for (int j = 0; j < 8; j++) {
                    mma16816(d[t][j], aH[t], bH[j]);
                    mma16816(d[t][j], aH[t], bL[j]);
                    mma16816(d[t][j], aL[t], bH[j]);
                }
        }
    }

    int er = lane >> 2;
    int ec = (lane & 3) * 2;
#pragma unroll
    for (int t = 0; t < 2; t++)
#pragma unroll
        for (int j = 0; j < 8; j++) {
            size_t row = arow0 + warp_m + t * 16 + er;
            size_t col = brow0 + warp_n + j * 8 + ec;
            float v0 = alpha * d[t][j][0], v1 = alpha * d[t][j][1];
            float v2 = alpha * d[t][j][2], v3 = alpha * d[t][j][3];
            if (Cf) {
                *(float2*)(Cf + row * 1024 + col)       = make_float2(v0, v1);
                *(float2*)(Cf + (row + 8) * 1024 + col) = make_float2(v2, v3);
            } else {
                *(__half2*)(Fo + row * 1024 + col)       = __floats2half2_rn(v0, v1);
                *(__half2*)(Fo + (row + 8) * 1024 + col) = __floats2half2_rn(v2, v3);
            }
        }
}

// ===========================================================================
// Tensor-core flash attention, single-term fp16 (8x less quantization error
// than the failed single-term bf16: predicted rel_err 2.31e-3/8 ~ 2.9e-4).
// Block = 64 queries, 4 warps, 128 threads; smem 36.9KB -> 4 CTAs/SM.
// ===========================================================================
#define AROWB 144                      // 72 fp16 per smem row
#define STAGE_BYTES (2 * 64 * AROWB)   // Kf,Vf tiles: 18432 B
#define ATT_SMEM_BYTES (2 * STAGE_BYTES)   // 36864 B
#define QTILE 64
#define ATH 128

__global__ __launch_bounds__(ATH, 4)
void attn_mma_kernel(const __half* __restrict__ Qf,
                     const __half* __restrict__ Kf,
                     const __half* __restrict__ Vf,
                     __nv_bfloat16* __restrict__ Ohi, __nv_bfloat16* __restrict__ Olo) {
    extern __shared__ char sm[];
    const uint32_t sb = smem_u32(sm);

    int tid = threadIdx.x;
    int w = tid >> 5, lane = tid & 31;
    int qt = blockIdx.x, h = blockIdx.y, b = blockIdx.z;

    const size_t qrow0 = (size_t)(b * S_ + qt * QTILE);
    const size_t krow0 = (size_t)(b * S_);
    const int    hc    = h * 64;

    // ---- Stage Q into stage-0: [64][72] fp16 = 9216 B
#pragma unroll
    for (int t = 0; t < 4; t++) {
        int rem = t * ATH + tid;             // 0..511
        int row = rem >> 3, ch = rem & 7;
        cp_async16(sb + row * AROWB + ch * 16,
                   Qf + (qrow0 + row) * 1024 + hc + ch * 8);
    }
    CP_COMMIT();
    CP_WAIT(0);
    __syncthreads();

    // ---- Q fragments to registers (held for whole kernel)
    int li = lane & 7, lt = lane >> 3;
    int qoff = ((lt & 1) * 8 + li) * AROWB + (lt >> 1) * 16;   // A-frag / trans-B addressing
    int koff = ((lt >> 1) * 8 + li) * AROWB + (lt & 1) * 16;   // B-frag addressing
    uint32_t qf[4][4];
#pragma unroll
    for (int kk = 0; kk < 4; kk++)
        ldmatrix_x4(qf[kk], sb + w * (16 * AROWB) + kk * 32 + qoff);
    __syncthreads();   // stage-0 free for K/V

    // ---- Prefetch key tile 0 -> stage 0 (Kf @0, Vf @9216)
#pragma unroll
    for (int t = 0; t < 8; t++) {
        int a = t >> 2;                      // 0: Kf, 1: Vf
        int rem = (t & 3) * ATH + tid;
        int row = rem >> 3, ch = rem & 7;
        const __half* src = a ? Vf : Kf;
        cp_async16(sb + a * 9216 + row * AROWB + ch * 16,
                   src + (krow0 + row) * 1024 + hc + ch * 8);
    }
    CP_COMMIT();

    float o[8][4];
#pragma unroll
    for (int n = 0; n < 8; n++)
#pragma unroll
        for (int e = 0; e < 4; e++) o[n][e] = 0.0f;
    float mA = -1e30f, mB = -1e30f, lA = 0.0f, lB = 0.0f;

    for (int kt = 0; kt < 32; kt++) {
        int cur = kt & 1;
        __syncthreads();
        if (kt + 1 < 32) {
            uint32_t nsb = sb + ((kt + 1) & 1) * STAGE_BYTES;
            size_t krow = krow0 + (size_t)(kt + 1) * 64;
#pragma unroll
            for (int t = 0; t < 8; t++) {
                int a = t >> 2;
                int rem = (t & 3) * ATH + tid;
                int row = rem >> 3, ch = rem & 7;
                const __half* src = a ? Vf : Kf;
                cp_async16(nsb + a * 9216 + row * AROWB + ch * 16,
                           src + (krow + row) * 1024 + hc + ch * 8);
            }
        }
        CP_COMMIT();
        CP_WAIT(1);        // current tile resident (groups retire in order)
        __syncthreads();

        uint32_t Kb = sb + cur * STAGE_BYTES;
        uint32_t Vb = Kb + 9216;

        // ---- S = Q K^T (fp16 single term). s[j]: n-tile j = keys 8j..8j+7
        float s[8][4];
#pragma unroll
        for (int j = 0; j < 8; j++)
#pragma unroll
            for (int e = 0; e < 4; e++) s[j][e] = 0.0f;

#pragma unroll
        for (int kk = 0; kk < 4; kk++)
#pragma unroll
            for (int jp = 0; jp < 4; jp++) {
                uint32_t k4[4];
                ldmatrix_x4(k4, Kb + jp * (16 * AROWB) + kk * 32 + koff);
                mma16816h(s[2 * jp],     qf[kk], k4);
                mma16816h(s[2 * jp + 1], qf[kk], k4 + 2);
            }

        // ---- Online softmax (rows g = lane>>2 and g+8)
        float mxA = -1e30f, mxB = -1e30f;
#pragma unroll
        for (int j = 0; j < 8; j++) {
            mxA = fmaxf(mxA, fmaxf(s[j][0], s[j][1]));
            mxB = fmaxf(mxB, fmaxf(s[j][2], s[j][3]));
        }
        mxA = fmaxf(mxA, __shfl_xor_sync(0xffffffffu, mxA, 1));
        mxA = fmaxf(mxA, __shfl_xor_sync(0xffffffffu, mxA, 2));
        mxB = fmaxf(mxB, __shfl_xor_sync(0xffffffffu, mxB, 1));
        mxB = fmaxf(mxB, __shfl_xor_sync(0xffffffffu, mxB, 2));
        float mnA = fmaxf(mA, mxA), mnB = fmaxf(mB, mxB);
        float corrA = fexp2(mA - mnA), corrB = fexp2(mB - mnB);
        mA = mnA; mB = mnB;

        float rsA = 0.0f, rsB = 0.0f;
        uint32_t ph[8][2];
#pragma unroll
        for (int j = 0; j < 8; j++) {
            float p0 = fexp2(s[j][0] - mnA);
            float p1 = fexp2(s[j][1] - mnA);
            float p2 = fexp2(s[j][2] - mnB);
            float p3 = fexp2(s[j][3] - mnB);
            rsA += p0 + p1;
            rsB += p2 + p3;
            ph[j][0] = packhf2(p0, p1);
            ph[j][1] = packhf2(p2, p3);
        }
        rsA += __shfl_xor_sync(0xffffffffu, rsA, 1);
        rsA += __shfl_xor_sync(0xffffffffu, rsA, 2);
        rsB += __shfl_xor_sync(0xffffffffu, rsB, 1);
        rsB += __shfl_xor_sync(0xffffffffu, rsB, 2);
        lA = lA * corrA + rsA;
        lB = lB * corrB + rsB;
#pragma unroll
        for (int n = 0; n < 8; n++) {
            o[n][0] *= corrA; o[n][1] *= corrA;
            o[n][2] *= corrB; o[n][3] *= corrB;
        }

        // ---- O += P V (fp16 single term). P frags from regs; V via ldmatrix.trans
#pragma unroll
        for (int kt2 = 0; kt2 < 4; kt2++) {
            uint32_t ah[4] = {ph[2 * kt2][0], ph[2 * kt2][1],
                              ph[2 * kt2 + 1][0], ph[2 * kt2 + 1][1]};
#pragma unroll
            for (int np = 0; np < 4; np++) {
                uint32_t v4[4];
                ldmatrix_x4t(v4, Vb + kt2 * (16 * AROWB) + np * 32 + qoff);
                mma16816h(o[2 * np],     ah, v4);
                mma16816h(o[2 * np + 1], ah, v4 + 2);
            }
        }
    }

    // ---- Epilogue: normalize, bf16-split, store oh/ol [M][1024]
    float invA = 1.0f / lA, invB = 1.0f / lB;
    int g = lane >> 2, ec = (lane & 3) * 2;
    size_t rowA = qrow0 + w * 16 + g;
    size_t rowB = rowA + 8;
#pragma unroll
    for (int n = 0; n < 8; n++) {
        size_t col = hc + n * 8 + ec;
        float v0 = o[n][0] * invA, v1 = o[n][1] * invA;
        float v2 = o[n][2] * invB, v3 = o[n][3] * invB;
        __nv_bfloat16 h0, l0, h1, l1, h2, l2, h3, l3;
        bf16split(v0, h0, l0); bf16split(v1, h1, l1);
        bf16split(v2, h2, l2); bf16split(v3, h3, l3);
        *(__nv_bfloat162*)(Ohi + rowA * 1024 + col) = __nv_bfloat162(h0, h1);
        *(__nv_bfloat162*)(Olo + rowA * 1024 + col) = __nv_bfloat162(l0, l1);
        *(__nv_bfloat162*)(Ohi + rowB * 1024 + col) = __nv_bfloat162(h2, h3);
        *(__nv_bfloat162*)(Olo + rowB * 1024 + col) = __nv_bfloat162(l2, l3);
    }
}

// ===========================================================================
extern "C" void kernel_launch(void* const* d_in, const int* in_sizes, int n_in,
                              void* d_out, int out_size) {
    const float* x  = (const float*)d_in[0];
    const float* Wq = (const float*)d_in[1];
    const float* Wk = (const float*)d_in[2];
    const float* Wv = (const float*)d_in[3];
    const float* Wo = (const float*)d_in[4];
    float* out = (float*)d_out;

    __half *qf, *kf, *vf;
    __nv_bfloat16 *oh, *ol, *xh, *xl, *wth, *wtl;
    cudaGetSymbolAddress((void**)&qf, g_qf);
    cudaGetSymbolAddress((void**)&kf, g_kf);
    cudaGetSymbolAddress((void**)&vf, g_vf);
    cudaGetSymbolAddress((void**)&oh, g_oh);
    cudaGetSymbolAddress((void**)&ol, g_ol);
    cudaGetSymbolAddress((void**)&xh, g_xh);
    cudaGetSymbolAddress((void**)&xl, g_xl);
    cudaGetSymbolAddress((void**)&wth, g_wth);
    cudaGetSymbolAddress((void**)&wtl, g_wtl);

    cudaFuncSetAttribute(gemm_mma_kernel,
                         cudaFuncAttributeMaxDynamicSharedMemorySize, GEMM_SMEM_BYTES);
    cudaFuncSetAttribute(attn_mma_kernel,
                         cudaFuncAttributeMaxDynamicSharedMemorySize, ATT_SMEM_BYTES);

    // 1. Split x into bf16 hi/lo
    split_kernel<<<(M_ * D_ / 4 + 255) / 256, 256>>>(x, xh, xl, M_ * D_ / 4);

    // 2. Transpose + split weights -> [n][k] bf16
    tsplit_kernel<<<dim3(32, 32, 4), 256>>>(Wq, Wk, Wv, Wo, wth, wtl);

    // 3. QKV projections (3-term bf16) -> fp16 single q/k/v (q scaled by QSCALE)
    gemm_mma_kernel<<<dim3(8, 32, 3), 256, GEMM_SMEM_BYTES>>>(
        xh, xl, wth, wtl, qf, kf, vf, nullptr, QSCALE);

    // 4. Tensor-core flash attention (single-term fp16, 4 CTAs/SM)
    attn_mma_kernel<<<dim3(S_ / QTILE, 16, 2), ATH, ATT_SMEM_BYTES>>>(
        qf, kf, vf, oh, ol);

    // 5. Output projection (3-term bf16) -> fp32 d_out
    gemm_mma_kernel<<<dim3(8, 32, 1), 256, GEMM_SMEM_BYTES>>>(
        oh, ol, wth + (size_t)3 * D_ * N_, wtl + (size_t)3 * D_ * N_,
        nullptr, nullptr, nullptr, out, 1.0f);
}